// round 1
// baseline (speedup 1.0000x reference)
#include <cuda_runtime.h>

// CapsuleLayer: x[B,I,D] fp32, W[I,O,D,K] fp32 -> v[B,O,K] fp32
// B=64, I=2048, D=8, O=32, K=16, 3 routing iterations.
//
// Key identity: routing logits are linear in v:
//   b_r[b,o,i] = sum_{t<r} u_hat[b,o,i,:] . v_t[b,o,:] = u_hat[b,o,i,:] . Vsum_r[b,o,:]
// so each routing round is ONE fused sweep over i recomputing u_hat in registers.

#define BB 64
#define II 2048
#define DD 8
#define OO 32
#define KK 16
#define BG 16   // b's per block
#define IC 8    // i's per block
#define SVOL (BB*OO*KK)   // 32768

__device__ float g_s[SVOL];     // s accumulator (pre-squash), per pass
__device__ float g_vsum[SVOL];  // running sum of squashed v's (for agreement)

__global__ void zero_kernel() {
    int idx = blockIdx.x * blockDim.x + threadIdx.x;
    if (idx < SVOL) { g_s[idx] = 0.0f; g_vsum[idx] = 0.0f; }
}

// Fused routing pass.
// Thread layout: t = o*16 + b_local  (512 threads = 32 o x 16 b).
// Warp = 2 o x 16 b -> W loads broadcast across the 16 b-lanes (L1-merged).
// Each thread owns u_hat[b,o,i,:] (16 regs) for the current i: computed ONCE,
// used for agreement AND for s-accumulation.
template<bool FIRST>
__global__ __launch_bounds__(512, 1)
void pass_kernel(const float* __restrict__ x, const float* __restrict__ W) {
    const int t  = threadIdx.x;
    const int o  = t >> 4;        // 0..31
    const int bl = t & 15;        // 0..15
    const int b  = blockIdx.y * BG + bl;
    const int i0 = blockIdx.x * IC;

    __shared__ float ag_sm[OO * BG];  // agreement staging [o][bl]
    __shared__ float es_sm[OO * BG];  // exp staging       [o][bl]

    float Vs[KK];
    if (!FIRST) {
        const float* vp = g_vsum + ((size_t)b * OO + o) * KK;
#pragma unroll
        for (int k = 0; k < KK; k++) Vs[k] = vp[k];
    }

    float sacc[KK];
#pragma unroll
    for (int k = 0; k < KK; k++) sacc[k] = 0.0f;

    for (int ii = 0; ii < IC; ii++) {
        const int i = i0 + ii;

        // x[b,i,:] : 8 floats (2x float4)
        const float4* xp = reinterpret_cast<const float4*>(x + ((size_t)b * II + i) * DD);
        float4 xa = xp[0], xb4 = xp[1];
        float xd[8] = {xa.x, xa.y, xa.z, xa.w, xb4.x, xb4.y, xb4.z, xb4.w};

        // W[i,o,:,:] : 128 contiguous floats (32x float4), layout [d][k]
        const float4* wp = reinterpret_cast<const float4*>(W + ((size_t)i * OO + o) * (DD * KK));

        // u_hat[b,o,i,k] = sum_d x[b,i,d] * W[i,o,d,k]
        float u[KK];
#pragma unroll
        for (int k = 0; k < KK; k++) u[k] = 0.0f;
#pragma unroll
        for (int d = 0; d < DD; d++) {
            const float xv = xd[d];
            float4 w0 = wp[d * 4 + 0];
            float4 w1 = wp[d * 4 + 1];
            float4 w2 = wp[d * 4 + 2];
            float4 w3 = wp[d * 4 + 3];
            u[0]  = fmaf(xv, w0.x, u[0]);  u[1]  = fmaf(xv, w0.y, u[1]);
            u[2]  = fmaf(xv, w0.z, u[2]);  u[3]  = fmaf(xv, w0.w, u[3]);
            u[4]  = fmaf(xv, w1.x, u[4]);  u[5]  = fmaf(xv, w1.y, u[5]);
            u[6]  = fmaf(xv, w1.z, u[6]);  u[7]  = fmaf(xv, w1.w, u[7]);
            u[8]  = fmaf(xv, w2.x, u[8]);  u[9]  = fmaf(xv, w2.y, u[9]);
            u[10] = fmaf(xv, w2.z, u[10]); u[11] = fmaf(xv, w2.w, u[11]);
            u[12] = fmaf(xv, w3.x, u[12]); u[13] = fmaf(xv, w3.y, u[13]);
            u[14] = fmaf(xv, w3.z, u[14]); u[15] = fmaf(xv, w3.w, u[15]);
        }

        float c;
        if (FIRST) {
            // softmax of all-zero logits over O = uniform 1/O
            c = 1.0f / (float)OO;
        } else {
            // agreement = u . Vsum
            float agr = 0.0f;
#pragma unroll
            for (int k = 0; k < KK; k++) agr = fmaf(u[k], Vs[k], agr);

            // softmax over o (cross-warp via smem; double buffer => 2 syncs)
            ag_sm[t] = agr;
            __syncthreads();
            float m = -3.0e38f;
#pragma unroll
            for (int oo = 0; oo < OO; oo++) m = fmaxf(m, ag_sm[oo * BG + bl]);
            float e = __expf(agr - m);
            es_sm[t] = e;
            __syncthreads();
            float ssum = 0.0f;
#pragma unroll
            for (int oo = 0; oo < OO; oo++) ssum += es_sm[oo * BG + bl];
            c = e / ssum;
        }

        // s[b,o,k] += c * u[k]
#pragma unroll
        for (int k = 0; k < KK; k++) sacc[k] = fmaf(c, u[k], sacc[k]);
    }

    // flush partial s (all (b,o,k) addresses distinct within a block)
    float* sp = g_s + ((size_t)b * OO + o) * KK;
#pragma unroll
    for (int k = 0; k < KK; k++) atomicAdd(sp + k, sacc[k]);
}

// squash over K=16 (aligned 16-lane groups within a warp).
// final_pass=0: Vsum += v, re-zero s for next pass.  final_pass=1: write d_out.
__global__ void squash_kernel(float* __restrict__ out, int final_pass) {
    int idx = blockIdx.x * blockDim.x + threadIdx.x;  // (b*O+o)*K + k
    float sv = g_s[idx];
    float s2 = sv * sv;
    s2 += __shfl_xor_sync(0xffffffffu, s2, 1);
    s2 += __shfl_xor_sync(0xffffffffu, s2, 2);
    s2 += __shfl_xor_sync(0xffffffffu, s2, 4);
    s2 += __shfl_xor_sync(0xffffffffu, s2, 8);
    float scale = (s2 / (1.0f + s2)) / sqrtf(s2 + 1e-7f);
    float v = scale * sv;
    if (final_pass) {
        out[idx] = v;
    } else {
        g_vsum[idx] += v;
        g_s[idx] = 0.0f;
    }
}

extern "C" void kernel_launch(void* const* d_in, const int* in_sizes, int n_in,
                              void* d_out, int out_size) {
    const float* a0 = (const float*)d_in[0];
    const float* a1 = (const float*)d_in[1];
    // Disambiguate by element count: x has B*I*D = 1048576, W has 8388608.
    const float* x;
    const float* W;
    if (in_sizes[0] == BB * II * DD) { x = a0; W = a1; }
    else                             { x = a1; W = a0; }
    float* out = (float*)d_out;

    dim3 pg(II / IC, BB / BG);   // (256, 4) blocks, 512 threads each
    const int rb = SVOL / 512;   // 64 blocks for reduction-sized kernels

    zero_kernel<<<rb, 512>>>();                 // reset scratch (every replay)

    pass_kernel<true><<<pg, 512>>>(x, W);       // s0 (uniform c)
    squash_kernel<<<rb, 512>>>(out, 0);         // v0 -> Vsum, zero s

    pass_kernel<false><<<pg, 512>>>(x, W);      // s1 (agreement vs Vsum=v0)
    squash_kernel<<<rb, 512>>>(out, 0);         // v1 -> Vsum, zero s

    pass_kernel<false><<<pg, 512>>>(x, W);      // s2 (agreement vs Vsum=v0+v1)
    squash_kernel<<<rb, 512>>>(out, 1);         // v2 = output
}

// round 2
// speedup vs baseline: 1.4599x; 1.4599x over previous
#include <cuda_runtime.h>

// CapsuleLayer: x[B,I,D] fp32, W[I,O,D,K] fp32 -> v[B,O,K] fp32
// B=64, I=2048, D=8, O=32, K=16, 3 routing rounds.
// Routing logits are linear in v:  b_r[b,o,i] = u_hat[b,o,i,:] . Vsum_r[b,o,:]
// => each round = ONE fused sweep over i recomputing u_hat in registers.

#define BB 64
#define II 2048
#define DD 8
#define OO 32
#define KK 16
#define BG 16          // b's per block
#define IC 16          // i's per block (i-tile)
#define NP (II/IC)     // 128 partial slabs
#define SVOL (BB*OO*KK) // 32768

__device__ float g_part[NP * SVOL];  // per-i-block partial s  (16.8 MB)
__device__ float g_vsum[SVOL];       // running sum of squashed v's

// ---------- packed f32x2 helpers ----------
__device__ __forceinline__ unsigned long long pk2(float lo, float hi) {
    unsigned long long r;
    asm("mov.b64 %0, {%1, %2};" : "=l"(r) : "f"(lo), "f"(hi));
    return r;
}
__device__ __forceinline__ void upk2(unsigned long long v, float& lo, float& hi) {
    asm("mov.b64 {%0, %1}, %2;" : "=f"(lo), "=f"(hi) : "l"(v));
}
__device__ __forceinline__ unsigned long long fma2(unsigned long long a,
                                                   unsigned long long b,
                                                   unsigned long long c) {
    unsigned long long d;
    asm("fma.rn.f32x2 %0, %1, %2, %3;" : "=l"(d) : "l"(a), "l"(b), "l"(c));
    return d;
}

// ---------- cp.async helpers ----------
__device__ __forceinline__ void cp16(unsigned dst_smem, const void* src) {
    asm volatile("cp.async.cg.shared.global [%0], [%1], 16;"
                 :: "r"(dst_smem), "l"(src));
}
__device__ __forceinline__ void cp_commit() {
    asm volatile("cp.async.commit_group;");
}
__device__ __forceinline__ void cp_wait0() {
    asm volatile("cp.async.wait_group 0;" ::: "memory");
}

// Fused routing pass.
// Threads: 512 = 32 o x 16 bl.  Warp = 2 o x 16 b (W smem reads broadcast).
// W tile for one i staged in smem (double-buffered, cp.async prefetch).
// u_hat[b,o,i,:] computed once per i in 8 packed-f32x2 registers.
template<bool FIRST>
__global__ __launch_bounds__(512, 1)
void pass_kernel(const float* __restrict__ x, const float* __restrict__ W) {
    const int t  = threadIdx.x;
    const int o  = t >> 4;
    const int bl = t & 15;
    const int b  = blockIdx.y * BG + bl;
    const int i0 = blockIdx.x * IC;

    // smem: W double buffer (pad: 33 float4 per o), x tile (12-float rows), ag row buf
    __shared__ float4 W_sm[2][OO * 33];        // 2 * 16896 B
    __shared__ float  x_sm[IC * BG * 12];      // 12288 B
    __shared__ float  ag_sm[BG * 33];          // 2112 B (reused for c)

    const unsigned Wsm_addr0 = (unsigned)__cvta_generic_to_shared(&W_sm[0][0]);
    const unsigned Wsm_addr1 = (unsigned)__cvta_generic_to_shared(&W_sm[1][0]);
    const unsigned xsm_addr  = (unsigned)__cvta_generic_to_shared(&x_sm[0]);

    // ---- prologue: stage x tile (1 chunk per thread) + W[i0] into buf0 ----
    {
        // x chunks: 512 = 16 ii * 16 bl * 2 halves
        int half = t & 1, xbl = (t >> 1) & 15, xi = t >> 5;
        const float* src = x + ((size_t)(blockIdx.y * BG + xbl) * II + (i0 + xi)) * DD + half * 4;
        cp16(xsm_addr + ((xi * BG + xbl) * 12 + half * 4) * 4, src);

        // W[i0]: 1024 float4 chunks, 2 per thread
        const float* wsrc = W + (size_t)i0 * (OO * DD * KK);
#pragma unroll
        for (int r = 0; r < 2; r++) {
            int j = t + r * 512;
            int jo = j >> 5, jw = j & 31;
            cp16(Wsm_addr0 + (jo * 33 + jw) * 16, wsrc + j * 4);
        }
        cp_commit();
    }

    // Vsum for this (b,o) as 8 packed pairs
    unsigned long long Vs2[8];
    if (!FIRST) {
        const ulonglong2* vp =
            reinterpret_cast<const ulonglong2*>(g_vsum + ((size_t)b * OO + o) * KK);
        ulonglong2 v0 = vp[0], v1 = vp[1], v2 = vp[2], v3 = vp[3];
        Vs2[0] = v0.x; Vs2[1] = v0.y; Vs2[2] = v1.x; Vs2[3] = v1.y;
        Vs2[4] = v2.x; Vs2[5] = v2.y; Vs2[6] = v3.x; Vs2[7] = v3.y;
    }

    unsigned long long sacc2[8];
#pragma unroll
    for (int j = 0; j < 8; j++) sacc2[j] = 0ull;

    const unsigned long long cu2 = pk2(1.0f / OO, 1.0f / OO);

    cp_wait0();
    __syncthreads();

    for (int ii = 0; ii < IC; ii++) {
        const int cur = ii & 1;

        // prefetch W[i+1] into the other buffer
        if (ii + 1 < IC) {
            const float* wsrc = W + (size_t)(i0 + ii + 1) * (OO * DD * KK);
            unsigned dstb = cur ? Wsm_addr0 : Wsm_addr1;
#pragma unroll
            for (int r = 0; r < 2; r++) {
                int j = t + r * 512;
                int jo = j >> 5, jw = j & 31;
                cp16(dstb + (jo * 33 + jw) * 16, wsrc + j * 4);
            }
        }
        cp_commit();

        // x[b, i, 0..7]
        float xf[8];
        {
            const float4* xr = reinterpret_cast<const float4*>(&x_sm[(ii * BG + bl) * 12]);
            float4 a = xr[0], c4 = xr[1];
            xf[0] = a.x;  xf[1] = a.y;  xf[2] = a.z;  xf[3] = a.w;
            xf[4] = c4.x; xf[5] = c4.y; xf[6] = c4.z; xf[7] = c4.w;
        }

        // u_hat: 8 packed pairs
        unsigned long long u2[8];
#pragma unroll
        for (int j = 0; j < 8; j++) u2[j] = 0ull;

        const float4* wbase = &W_sm[cur][o * 33];
#pragma unroll
        for (int d = 0; d < DD; d++) {
            unsigned long long x2 = pk2(xf[d], xf[d]);
            const ulonglong2* wp = reinterpret_cast<const ulonglong2*>(wbase + d * 4);
            ulonglong2 wa = wp[0], wb4 = wp[1], wc4 = wp[2], wd4 = wp[3];
            u2[0] = fma2(x2, wa.x,  u2[0]);
            u2[1] = fma2(x2, wa.y,  u2[1]);
            u2[2] = fma2(x2, wb4.x, u2[2]);
            u2[3] = fma2(x2, wb4.y, u2[3]);
            u2[4] = fma2(x2, wc4.x, u2[4]);
            u2[5] = fma2(x2, wc4.y, u2[5]);
            u2[6] = fma2(x2, wd4.x, u2[6]);
            u2[7] = fma2(x2, wd4.y, u2[7]);
        }

        unsigned long long c2;
        if (FIRST) {
            c2 = cu2;
            cp_wait0();
            __syncthreads();
        } else {
            // agreement = u . Vsum
            unsigned long long acc = 0ull;
#pragma unroll
            for (int j = 0; j < 8; j++) acc = fma2(u2[j], Vs2[j], acc);
            float alo, ahi;
            upk2(acc, alo, ahi);
            ag_sm[bl * 33 + o] = alo + ahi;
            __syncthreads();

            // warp w handles softmax for b-row w (16 warps, 16 rows)
            {
                int w = t >> 5, lane = t & 31;
                float av = ag_sm[w * 33 + lane];
                float m = av;
#pragma unroll
                for (int s = 16; s > 0; s >>= 1)
                    m = fmaxf(m, __shfl_xor_sync(0xffffffffu, m, s));
                float e = __expf(av - m);
                float ssum = e;
#pragma unroll
                for (int s = 16; s > 0; s >>= 1)
                    ssum += __shfl_xor_sync(0xffffffffu, ssum, s);
                ag_sm[w * 33 + lane] = __fdividef(e, ssum);
            }
            cp_wait0();
            __syncthreads();

            float c = ag_sm[bl * 33 + o];
            c2 = pk2(c, c);
        }

        // s += c * u
#pragma unroll
        for (int j = 0; j < 8; j++) sacc2[j] = fma2(c2, u2[j], sacc2[j]);
    }

    // flush partial s for this i-block (no atomics)
    ulonglong2* pp = reinterpret_cast<ulonglong2*>(
        g_part + ((size_t)blockIdx.x * BB * OO + (size_t)b * OO + o) * KK);
    pp[0] = make_ulonglong2(sacc2[0], sacc2[1]);
    pp[1] = make_ulonglong2(sacc2[2], sacc2[3]);
    pp[2] = make_ulonglong2(sacc2[4], sacc2[5]);
    pp[3] = make_ulonglong2(sacc2[6], sacc2[7]);
}

// Reduce partials over NP i-blocks, squash over K=16, update Vsum / write out.
// phase 0: vsum = v ; phase 1: vsum += v ; phase 2: out = v
__global__ void squash_kernel(float* __restrict__ out, int phase) {
    int idx = blockIdx.x * 512 + threadIdx.x;   // (b*O+o)*K + k
    float s = 0.0f;
#pragma unroll 8
    for (int p = 0; p < NP; p++) s += g_part[(size_t)p * SVOL + idx];

    float s2 = s * s;
    s2 += __shfl_xor_sync(0xffffffffu, s2, 1);
    s2 += __shfl_xor_sync(0xffffffffu, s2, 2);
    s2 += __shfl_xor_sync(0xffffffffu, s2, 4);
    s2 += __shfl_xor_sync(0xffffffffu, s2, 8);

    float scale = s2 / ((1.0f + s2) * sqrtf(s2 + 1e-7f));
    float v = scale * s;

    if (phase == 0)      g_vsum[idx] = v;
    else if (phase == 1) g_vsum[idx] += v;
    else                 out[idx] = v;
}

extern "C" void kernel_launch(void* const* d_in, const int* in_sizes, int n_in,
                              void* d_out, int out_size) {
    const float* a0 = (const float*)d_in[0];
    const float* a1 = (const float*)d_in[1];
    const float* x;
    const float* W;
    if (in_sizes[0] == BB * II * DD) { x = a0; W = a1; }
    else                             { x = a1; W = a0; }
    float* out = (float*)d_out;

    dim3 pg(II / IC, BB / BG);     // (128, 4) blocks, 512 threads
    const int rb = SVOL / 512;     // 64 blocks

    pass_kernel<true><<<pg, 512>>>(x, W);    // s0 (uniform c)
    squash_kernel<<<rb, 512>>>(out, 0);      // v0 -> Vsum

    pass_kernel<false><<<pg, 512>>>(x, W);   // s1 (agreement vs v0)
    squash_kernel<<<rb, 512>>>(out, 1);      // Vsum += v1

    pass_kernel<false><<<pg, 512>>>(x, W);   // s2 (agreement vs v0+v1)
    squash_kernel<<<rb, 512>>>(out, 2);      // v2 = output
}

// round 3
// speedup vs baseline: 1.6788x; 1.1499x over previous
#include <cuda_runtime.h>

// CapsuleLayer: x[B,I,D] fp32, W[I,O,D,K] fp32 -> v[B,O,K] fp32
// B=64, I=2048, D=8, O=32, K=16, 3 routing rounds.
// Routing logits are linear in v:  b_r[b,o,i] = u_hat[b,o,i,:] . Vsum_r[b,o,:]
// => each round = ONE fused sweep over i recomputing u_hat in registers.

#define BB 64
#define II 2048
#define DD 8
#define OO 32
#define KK 16
#define BG 16            // b's per block
#define IC 64            // i's per block
#define NP (II/IC)       // 32 partial slabs
#define SVOL (BB*OO*KK)  // 32768
#define NSTAGE 4
#define WROW 132         // padded row stride (floats) for W smem rows

// smem layout (dynamic):
//   W   : NSTAGE stages x 16 warps x 2 rows x WROW floats
//   x   : IC x BG rows x 12 floats (padded)
//   ag  : BG x 33 floats
#define W_BYTES   (NSTAGE * 16 * 2 * WROW * 4)        // 67584
#define X_OFF     W_BYTES
#define X_BYTES   (IC * BG * 12 * 4)                  // 49152
#define AG_OFF    (X_OFF + X_BYTES)
#define AG_BYTES  (BG * 33 * 4)                       // 2112
#define SMEM_TOTAL (AG_OFF + AG_BYTES)                // 118848

__device__ float g_part[NP * SVOL];  // per-i-block partial s (4.2 MB)
__device__ float g_vsum[SVOL];       // running sum of squashed v's

// ---------- packed f32x2 helpers ----------
__device__ __forceinline__ unsigned long long pk2(float lo, float hi) {
    unsigned long long r;
    asm("mov.b64 %0, {%1, %2};" : "=l"(r) : "f"(lo), "f"(hi));
    return r;
}
__device__ __forceinline__ void upk2(unsigned long long v, float& lo, float& hi) {
    asm("mov.b64 {%0, %1}, %2;" : "=f"(lo), "=f"(hi) : "l"(v));
}
__device__ __forceinline__ unsigned long long fma2(unsigned long long a,
                                                   unsigned long long b,
                                                   unsigned long long c) {
    unsigned long long d;
    asm("fma.rn.f32x2 %0, %1, %2, %3;" : "=l"(d) : "l"(a), "l"(b), "l"(c));
    return d;
}

// ---------- cp.async helpers ----------
__device__ __forceinline__ void cp16(unsigned dst_smem, const void* src) {
    asm volatile("cp.async.cg.shared.global [%0], [%1], 16;"
                 :: "r"(dst_smem), "l"(src));
}
__device__ __forceinline__ void cp_commit() {
    asm volatile("cp.async.commit_group;");
}
template<int N>
__device__ __forceinline__ void cp_wait() {
    asm volatile("cp.async.wait_group %0;" :: "n"(N) : "memory");
}

// Warp w stages its own o-rows {2w, 2w+1} of W[i] (1056 B per stage).
__device__ __forceinline__ void stage_W(unsigned wbase_sm, const float* __restrict__ W,
                                        int i, int w, int lane, int stage) {
    unsigned dst = wbase_sm + ((stage * 16 + w) * 2) * (WROW * 4) + lane * 16;
    const float* src = W + (((size_t)i * OO + 2 * w) * (DD * KK)) + lane * 4;
#pragma unroll
    for (int r = 0; r < 2; r++)
        cp16(dst + r * (WROW * 4), src + r * (DD * KK));
    cp_commit();
}

// Fused routing pass. 512 threads = 32 o x 16 bl. Warp = 2 o x 16 b.
template<bool FIRST>
__global__ __launch_bounds__(512, 1)
void pass_kernel(const float* __restrict__ x, const float* __restrict__ W) {
    extern __shared__ char smem[];
    float* W_sm = reinterpret_cast<float*>(smem);
    float* x_sm = reinterpret_cast<float*>(smem + X_OFF);
    float* ag_sm = reinterpret_cast<float*>(smem + AG_OFF);

    const int t    = threadIdx.x;
    const int o    = t >> 4;
    const int bl   = t & 15;
    const int w    = t >> 5;
    const int lane = t & 31;
    const int b    = blockIdx.y * BG + bl;
    const int i0   = blockIdx.x * IC;

    const unsigned Wsm_addr = (unsigned)__cvta_generic_to_shared(W_sm);
    const unsigned xsm_addr = (unsigned)__cvta_generic_to_shared(x_sm);

    // ---- prologue ----
    // G0: x tile (IC x BG x 8 floats -> padded 12-float rows). 2048 chunks / 512 thr = 4 each.
    {
#pragma unroll
        for (int r = 0; r < 4; r++) {
            int c = t + r * 512;
            int xi = c >> 5, xbl = (c >> 1) & 15, half = c & 1;
            const float* src = x + ((size_t)(blockIdx.y * BG + xbl) * II + (i0 + xi)) * DD + half * 4;
            cp16(xsm_addr + ((xi * BG + xbl) * 12 + half * 4) * 4, src);
        }
        cp_commit();
    }
    // G1..G3: W[i0..i0+2], per-warp rows
    stage_W(Wsm_addr, W, i0 + 0, w, lane, 0);
    stage_W(Wsm_addr, W, i0 + 1, w, lane, 1);
    stage_W(Wsm_addr, W, i0 + 2, w, lane, 2);

    // Vsum for this (b,o) as 8 packed pairs
    unsigned long long Vs2[8];
    if (!FIRST) {
        const ulonglong2* vp =
            reinterpret_cast<const ulonglong2*>(g_vsum + ((size_t)b * OO + o) * KK);
        ulonglong2 v0 = vp[0], v1 = vp[1], v2 = vp[2], v3 = vp[3];
        Vs2[0] = v0.x; Vs2[1] = v0.y; Vs2[2] = v1.x; Vs2[3] = v1.y;
        Vs2[4] = v2.x; Vs2[5] = v2.y; Vs2[6] = v3.x; Vs2[7] = v3.y;
    }

    unsigned long long sacc2[8];
#pragma unroll
    for (int j = 0; j < 8; j++) sacc2[j] = 0ull;

    cp_wait<3>();        // x tile (G0) done; W stages may still be in flight
    __syncthreads();     // x visible block-wide

    for (int ii = 0; ii < IC; ii++) {
        const int stage = ii & 3;

        // prefetch W[ii+3] into stage (ii+3)&3 (per-warp, no block sync needed)
        if (ii + 3 < IC) {
            stage_W(Wsm_addr, W, i0 + ii + 3, w, lane, (ii + 3) & 3);
            cp_wait<3>();
        } else {
            int pending = IC - 1 - ii;     // groups still wanted in flight
            if (pending >= 3)      cp_wait<3>();
            else if (pending == 2) cp_wait<2>();
            else if (pending == 1) cp_wait<1>();
            else                   cp_wait<0>();
        }
        __syncwarp();    // make other lanes' cp.async for this stage visible

        // x[b, i, 0..7]
        float xf[8];
        {
            const float4* xr = reinterpret_cast<const float4*>(&x_sm[(ii * BG + bl) * 12]);
            float4 a = xr[0], c4 = xr[1];
            xf[0] = a.x;  xf[1] = a.y;  xf[2] = a.z;  xf[3] = a.w;
            xf[4] = c4.x; xf[5] = c4.y; xf[6] = c4.z; xf[7] = c4.w;
        }

        // u_hat: 8 packed pairs
        unsigned long long u2[8];
#pragma unroll
        for (int j = 0; j < 8; j++) u2[j] = 0ull;

        const float* wrow = W_sm + ((stage * 16 + w) * 2 + (o & 1)) * WROW;
#pragma unroll
        for (int d = 0; d < DD; d++) {
            unsigned long long x2 = pk2(xf[d], xf[d]);
            const ulonglong2* wp = reinterpret_cast<const ulonglong2*>(wrow + d * 16);
            ulonglong2 wa = wp[0], wb4 = wp[1];
            u2[0] = fma2(x2, wa.x,  u2[0]);
            u2[1] = fma2(x2, wa.y,  u2[1]);
            u2[2] = fma2(x2, wb4.x, u2[2]);
            u2[3] = fma2(x2, wb4.y, u2[3]);
            ulonglong2 wc4 = wp[2], wd4 = wp[3];
            u2[4] = fma2(x2, wc4.x, u2[4]);
            u2[5] = fma2(x2, wc4.y, u2[5]);
            u2[6] = fma2(x2, wd4.x, u2[6]);
            u2[7] = fma2(x2, wd4.y, u2[7]);
        }

        unsigned long long c2;
        if (FIRST) {
            c2 = pk2(1.0f / OO, 1.0f / OO);
        } else {
            // agreement = u . Vsum
            unsigned long long acc = 0ull;
#pragma unroll
            for (int j = 0; j < 8; j++) acc = fma2(u2[j], Vs2[j], acc);
            float alo, ahi;
            upk2(acc, alo, ahi);
            ag_sm[bl * 33 + o] = alo + ahi;
            __syncthreads();

            // warp w does softmax for b-row w (16 warps = 16 rows, lane = o)
            {
                float av = ag_sm[w * 33 + lane];
                float m = av;
#pragma unroll
                for (int s = 16; s > 0; s >>= 1)
                    m = fmaxf(m, __shfl_xor_sync(0xffffffffu, m, s));
                float e = __expf(av - m);
                float ssum = e;
#pragma unroll
                for (int s = 16; s > 0; s >>= 1)
                    ssum += __shfl_xor_sync(0xffffffffu, ssum, s);
                ag_sm[w * 33 + lane] = __fdividef(e, ssum);
            }
            __syncthreads();

            float c = ag_sm[bl * 33 + o];
            c2 = pk2(c, c);
        }

        // s += c * u
#pragma unroll
        for (int j = 0; j < 8; j++) sacc2[j] = fma2(c2, u2[j], sacc2[j]);
    }

    // flush partial s for this i-block
    ulonglong2* pp = reinterpret_cast<ulonglong2*>(
        g_part + ((size_t)blockIdx.x * SVOL + ((size_t)b * OO + o) * KK));
    pp[0] = make_ulonglong2(sacc2[0], sacc2[1]);
    pp[1] = make_ulonglong2(sacc2[2], sacc2[3]);
    pp[2] = make_ulonglong2(sacc2[4], sacc2[5]);
    pp[3] = make_ulonglong2(sacc2[6], sacc2[7]);
}

// Reduce partials over NP slabs, squash over K=16, update Vsum / write out.
// phase 0: vsum = v ; phase 1: vsum += v ; phase 2: out = v
__global__ void squash_kernel(float* __restrict__ out, int phase) {
    int idx = blockIdx.x * 256 + threadIdx.x;   // (b*O+o)*K + k
    float s = 0.0f;
#pragma unroll
    for (int p = 0; p < NP; p++) s += g_part[(size_t)p * SVOL + idx];

    float s2 = s * s;
    s2 += __shfl_xor_sync(0xffffffffu, s2, 1);
    s2 += __shfl_xor_sync(0xffffffffu, s2, 2);
    s2 += __shfl_xor_sync(0xffffffffu, s2, 4);
    s2 += __shfl_xor_sync(0xffffffffu, s2, 8);

    float scale = s2 / ((1.0f + s2) * sqrtf(s2 + 1e-7f));
    float v = scale * s;

    if (phase == 0)      g_vsum[idx] = v;
    else if (phase == 1) g_vsum[idx] += v;
    else                 out[idx] = v;
}

extern "C" void kernel_launch(void* const* d_in, const int* in_sizes, int n_in,
                              void* d_out, int out_size) {
    const float* a0 = (const float*)d_in[0];
    const float* a1 = (const float*)d_in[1];
    const float* x;
    const float* W;
    if (in_sizes[0] == BB * II * DD) { x = a0; W = a1; }
    else                             { x = a1; W = a0; }
    float* out = (float*)d_out;

    // allow >48KB dynamic smem (idempotent; not a stream op, capture-safe)
    cudaFuncSetAttribute(pass_kernel<true>,
                         cudaFuncAttributeMaxDynamicSharedMemorySize, SMEM_TOTAL);
    cudaFuncSetAttribute(pass_kernel<false>,
                         cudaFuncAttributeMaxDynamicSharedMemorySize, SMEM_TOTAL);

    dim3 pg(II / IC, BB / BG);     // (32, 4) = 128 blocks, 512 threads
    const int rb = SVOL / 256;     // 128 blocks for squash

    pass_kernel<true><<<pg, 512, SMEM_TOTAL>>>(x, W);    // s0 (uniform c)
    squash_kernel<<<rb, 256>>>(out, 0);                  // v0 -> Vsum

    pass_kernel<false><<<pg, 512, SMEM_TOTAL>>>(x, W);   // s1 (vs v0)
    squash_kernel<<<rb, 256>>>(out, 1);                  // Vsum += v1

    pass_kernel<false><<<pg, 512, SMEM_TOTAL>>>(x, W);   // s2 (vs v0+v1)
    squash_kernel<<<rb, 256>>>(out, 2);                  // v2 = output
}

// round 4
// speedup vs baseline: 3.5651x; 2.1236x over previous
#include <cuda_runtime.h>

// CapsuleLayer: x[B,I,D] fp32, W[I,O,D,K] fp32 -> v[B,O,K] fp32
// B=64, I=2048, D=8, O=32, K=16, 3 routing rounds.
// Routing logits are linear in v:  b_r[b,o,i] = u_hat[b,o,i,:] . Vsum_r[b,o,:]
// => each round = ONE fused sweep over i recomputing u_hat in registers.
// This round: 2 b's per thread so each W shared-load feeds 2 batches
// (smem crossbar instruction count was the binding pipe).

#define BB 64
#define II 2048
#define DD 8
#define OO 32
#define KK 16
#define BG 32            // b's per block (2 per thread)
#define IC 32            // i's per block
#define SUB 2            // i's per slab
#define NSLAB (IC/SUB)   // 16
#define NBUF 3
#define NP (II/IC)       // 64 partial slabs
#define SVOL (BB*OO*KK)  // 32768

#define WROWF 132                    // padded floats per o-row
#define WSLABF (SUB*OO*WROWF)        // 8448 floats
#define XROWF 12
#define XSLABF (SUB*BG*XROWF)        // 768 floats
#define SLABF  (WSLABF + XSLABF)     // 9216 floats
#define AG_OFF (NBUF*SLABF)          // floats
#define AGROW  34
#define SMEM_BYTES ((AG_OFF + BG*AGROW) * 4)   // ~115 KB

__device__ float g_part[NP * SVOL];  // per-i-block partial s (8.4 MB)
__device__ float g_vsum[SVOL];       // running sum of squashed v's

// ---------- packed f32x2 helpers ----------
__device__ __forceinline__ unsigned long long pk2(float lo, float hi) {
    unsigned long long r;
    asm("mov.b64 %0, {%1, %2};" : "=l"(r) : "f"(lo), "f"(hi));
    return r;
}
__device__ __forceinline__ void upk2(unsigned long long v, float& lo, float& hi) {
    asm("mov.b64 {%0, %1}, %2;" : "=f"(lo), "=f"(hi) : "l"(v));
}
__device__ __forceinline__ unsigned long long fma2(unsigned long long a,
                                                   unsigned long long b,
                                                   unsigned long long c) {
    unsigned long long d;
    asm("fma.rn.f32x2 %0, %1, %2, %3;" : "=l"(d) : "l"(a), "l"(b), "l"(c));
    return d;
}

// ---------- cp.async helpers ----------
__device__ __forceinline__ void cp16(unsigned dst_smem, const void* src) {
    asm volatile("cp.async.cg.shared.global [%0], [%1], 16;"
                 :: "r"(dst_smem), "l"(src));
}
__device__ __forceinline__ void cp_commit() {
    asm volatile("cp.async.commit_group;");
}
template<int N>
__device__ __forceinline__ void cp_wait() {
    asm volatile("cp.async.wait_group %0;" :: "n"(N) : "memory");
}

// Stage one slab (SUB i's of W + x) into buffer `buf`. One commit group.
__device__ __forceinline__ void fill_slab(unsigned sm_addr,
                                          const float* __restrict__ W,
                                          const float* __restrict__ x,
                                          int i_base, int buf, int t, int bg) {
    // W: SUB * 1024 = 2048 float4 chunks, 4 per thread
#pragma unroll
    for (int r = 0; r < 4; r++) {
        int c = t + r * 512;
        int isub = c >> 10, rem = c & 1023;
        int o = rem >> 5, w16 = rem & 31;
        const float* src = W + ((size_t)(i_base + isub) * OO + o) * (DD * KK) + w16 * 4;
        unsigned dst = sm_addr +
            (unsigned)((buf * SLABF + isub * (OO * WROWF) + o * WROWF + w16 * 4) * 4);
        cp16(dst, src);
    }
    // x: SUB * BG * 2 = 128 float4 chunks, threads 0..127
    if (t < SUB * BG * 2) {
        int isub = t >> 6, b = (t >> 1) & 31, half = t & 1;
        const float* src = x + ((size_t)(bg * BG + b) * II + (i_base + isub)) * DD + half * 4;
        unsigned dst = sm_addr +
            (unsigned)((buf * SLABF + WSLABF + isub * (BG * XROWF) + b * XROWF + half * 4) * 4);
        cp16(dst, src);
    }
    cp_commit();
}

// Fused routing pass. 512 threads: t = o*16 + tb; thread handles b = tb, tb+16.
template<bool FIRST>
__global__ __launch_bounds__(512, 1)
void pass_kernel(const float* __restrict__ x, const float* __restrict__ W) {
    extern __shared__ float sm[];
    const unsigned sm_addr = (unsigned)__cvta_generic_to_shared(sm);
    float* ag = sm + AG_OFF;

    const int t  = threadIdx.x;
    const int o  = t >> 4;
    const int tb = t & 15;
    const int bg = blockIdx.y;
    const int b0 = bg * BG + tb;
    const int b1 = b0 + 16;
    const int i0 = blockIdx.x * IC;

    // prologue: slabs 0,1
    fill_slab(sm_addr, W, x, i0,        0, t, bg);
    fill_slab(sm_addr, W, x, i0 + SUB,  1, t, bg);

    // Vsum for (b0,o) and (b1,o), packed
    unsigned long long Va[8], Vb[8];
    if (!FIRST) {
        const ulonglong2* vp0 =
            reinterpret_cast<const ulonglong2*>(g_vsum + ((size_t)b0 * OO + o) * KK);
        const ulonglong2* vp1 =
            reinterpret_cast<const ulonglong2*>(g_vsum + ((size_t)b1 * OO + o) * KK);
#pragma unroll
        for (int j = 0; j < 4; j++) {
            ulonglong2 q0 = vp0[j]; Va[2*j] = q0.x; Va[2*j+1] = q0.y;
            ulonglong2 q1 = vp1[j]; Vb[2*j] = q1.x; Vb[2*j+1] = q1.y;
        }
    }

    unsigned long long sa[8], sb[8];
#pragma unroll
    for (int j = 0; j < 8; j++) { sa[j] = 0ull; sb[j] = 0ull; }

    for (int s = 0; s < NSLAB; s++) {
        if (s + 1 < NSLAB) cp_wait<1>(); else cp_wait<0>();
        __syncthreads();   // slab s resident; all warps done with slab s-1
        if (s + 2 < NSLAB)
            fill_slab(sm_addr, W, x, i0 + (s + 2) * SUB, (s + 2) % NBUF, t, bg);

        const int buf = s % NBUF;
        const float* slab = sm + buf * SLABF;

#pragma unroll
        for (int isub = 0; isub < SUB; isub++) {
            // x rows for b0, b1
            float xf0[8], xf1[8];
            {
                const float4* xr0 = reinterpret_cast<const float4*>(
                    slab + WSLABF + isub * (BG * XROWF) + tb * XROWF);
                const float4* xr1 = reinterpret_cast<const float4*>(
                    slab + WSLABF + isub * (BG * XROWF) + (tb + 16) * XROWF);
                float4 a0 = xr0[0], a1 = xr0[1];
                float4 c0 = xr1[0], c1 = xr1[1];
                xf0[0]=a0.x; xf0[1]=a0.y; xf0[2]=a0.z; xf0[3]=a0.w;
                xf0[4]=a1.x; xf0[5]=a1.y; xf0[6]=a1.z; xf0[7]=a1.w;
                xf1[0]=c0.x; xf1[1]=c0.y; xf1[2]=c0.z; xf1[3]=c0.w;
                xf1[4]=c1.x; xf1[5]=c1.y; xf1[6]=c1.z; xf1[7]=c1.w;
            }

            unsigned long long ua[8], ub[8];
#pragma unroll
            for (int j = 0; j < 8; j++) { ua[j] = 0ull; ub[j] = 0ull; }

            const float* wrow = slab + isub * (OO * WROWF) + o * WROWF;
#pragma unroll
            for (int d = 0; d < DD; d++) {
                const ulonglong2* wp = reinterpret_cast<const ulonglong2*>(wrow + d * 16);
                unsigned long long xa2 = pk2(xf0[d], xf0[d]);
                unsigned long long xb2 = pk2(xf1[d], xf1[d]);
                ulonglong2 q0 = wp[0], q1 = wp[1];
                ua[0] = fma2(xa2, q0.x, ua[0]);  ub[0] = fma2(xb2, q0.x, ub[0]);
                ua[1] = fma2(xa2, q0.y, ua[1]);  ub[1] = fma2(xb2, q0.y, ub[1]);
                ua[2] = fma2(xa2, q1.x, ua[2]);  ub[2] = fma2(xb2, q1.x, ub[2]);
                ua[3] = fma2(xa2, q1.y, ua[3]);  ub[3] = fma2(xb2, q1.y, ub[3]);
                ulonglong2 q2 = wp[2], q3 = wp[3];
                ua[4] = fma2(xa2, q2.x, ua[4]);  ub[4] = fma2(xb2, q2.x, ub[4]);
                ua[5] = fma2(xa2, q2.y, ua[5]);  ub[5] = fma2(xb2, q2.y, ub[5]);
                ua[6] = fma2(xa2, q3.x, ua[6]);  ub[6] = fma2(xb2, q3.x, ub[6]);
                ua[7] = fma2(xa2, q3.y, ua[7]);  ub[7] = fma2(xb2, q3.y, ub[7]);
            }

            unsigned long long c2a, c2b;
            if (FIRST) {
                c2a = pk2(1.0f / OO, 1.0f / OO);
                c2b = c2a;
            } else {
                unsigned long long acca = 0ull, accb = 0ull;
#pragma unroll
                for (int j = 0; j < 8; j++) {
                    acca = fma2(ua[j], Va[j], acca);
                    accb = fma2(ub[j], Vb[j], accb);
                }
                float al, ah, bl2, bh;
                upk2(acca, al, ah);
                upk2(accb, bl2, bh);
                ag[tb * AGROW + o]        = al + ah;
                ag[(tb + 16) * AGROW + o] = bl2 + bh;
                __syncthreads();

                // warp w: softmax rows w and w+16 (lane = o)
                {
                    int w = t >> 5, lane = t & 31;
                    float v0 = ag[w * AGROW + lane];
                    float v1 = ag[(w + 16) * AGROW + lane];
                    float m0 = v0, m1 = v1;
#pragma unroll
                    for (int st = 16; st > 0; st >>= 1) {
                        m0 = fmaxf(m0, __shfl_xor_sync(0xffffffffu, m0, st));
                        m1 = fmaxf(m1, __shfl_xor_sync(0xffffffffu, m1, st));
                    }
                    float e0 = __expf(v0 - m0), e1 = __expf(v1 - m1);
                    float s0 = e0, s1 = e1;
#pragma unroll
                    for (int st = 16; st > 0; st >>= 1) {
                        s0 += __shfl_xor_sync(0xffffffffu, s0, st);
                        s1 += __shfl_xor_sync(0xffffffffu, s1, st);
                    }
                    ag[w * AGROW + lane]        = __fdividef(e0, s0);
                    ag[(w + 16) * AGROW + lane] = __fdividef(e1, s1);
                }
                __syncthreads();

                float ca = ag[tb * AGROW + o];
                float cb = ag[(tb + 16) * AGROW + o];
                c2a = pk2(ca, ca);
                c2b = pk2(cb, cb);
            }

#pragma unroll
            for (int j = 0; j < 8; j++) {
                sa[j] = fma2(c2a, ua[j], sa[j]);
                sb[j] = fma2(c2b, ub[j], sb[j]);
            }
        }
    }

    // flush partials
    ulonglong2* p0 = reinterpret_cast<ulonglong2*>(
        g_part + ((size_t)blockIdx.x * SVOL + ((size_t)b0 * OO + o) * KK));
    ulonglong2* p1 = reinterpret_cast<ulonglong2*>(
        g_part + ((size_t)blockIdx.x * SVOL + ((size_t)b1 * OO + o) * KK));
    p0[0] = make_ulonglong2(sa[0], sa[1]);
    p0[1] = make_ulonglong2(sa[2], sa[3]);
    p0[2] = make_ulonglong2(sa[4], sa[5]);
    p0[3] = make_ulonglong2(sa[6], sa[7]);
    p1[0] = make_ulonglong2(sb[0], sb[1]);
    p1[1] = make_ulonglong2(sb[2], sb[3]);
    p1[2] = make_ulonglong2(sb[4], sb[5]);
    p1[3] = make_ulonglong2(sb[6], sb[7]);
}

// Reduce partials over NP slabs, squash over K=16, update Vsum / write out.
// phase 0: vsum = v ; phase 1: vsum += v ; phase 2: out = v
__global__ void squash_kernel(float* __restrict__ out, int phase) {
    int idx = blockIdx.x * 256 + threadIdx.x;   // (b*O+o)*K + k
    float s = 0.0f;
#pragma unroll
    for (int p = 0; p < NP; p++) s += g_part[(size_t)p * SVOL + idx];

    float s2 = s * s;
    s2 += __shfl_xor_sync(0xffffffffu, s2, 1);
    s2 += __shfl_xor_sync(0xffffffffu, s2, 2);
    s2 += __shfl_xor_sync(0xffffffffu, s2, 4);
    s2 += __shfl_xor_sync(0xffffffffu, s2, 8);

    float scale = s2 / ((1.0f + s2) * sqrtf(s2 + 1e-7f));
    float v = scale * s;

    if (phase == 0)      g_vsum[idx] = v;
    else if (phase == 1) g_vsum[idx] += v;
    else                 out[idx] = v;
}

extern "C" void kernel_launch(void* const* d_in, const int* in_sizes, int n_in,
                              void* d_out, int out_size) {
    const float* a0 = (const float*)d_in[0];
    const float* a1 = (const float*)d_in[1];
    const float* x;
    const float* W;
    if (in_sizes[0] == BB * II * DD) { x = a0; W = a1; }
    else                             { x = a1; W = a0; }
    float* out = (float*)d_out;

    cudaFuncSetAttribute(pass_kernel<true>,
                         cudaFuncAttributeMaxDynamicSharedMemorySize, SMEM_BYTES);
    cudaFuncSetAttribute(pass_kernel<false>,
                         cudaFuncAttributeMaxDynamicSharedMemorySize, SMEM_BYTES);

    dim3 pg(II / IC, BB / BG);     // (64, 2) = 128 blocks, 512 threads
    const int rb = SVOL / 256;     // 128 blocks for squash

    pass_kernel<true><<<pg, 512, SMEM_BYTES>>>(x, W);    // s0 (uniform c)
    squash_kernel<<<rb, 256>>>(out, 0);                  // v0 -> Vsum

    pass_kernel<false><<<pg, 512, SMEM_BYTES>>>(x, W);   // s1 (vs v0)
    squash_kernel<<<rb, 256>>>(out, 1);                  // Vsum += v1

    pass_kernel<false><<<pg, 512, SMEM_BYTES>>>(x, W);   // s2 (vs v0+v1)
    squash_kernel<<<rb, 256>>>(out, 2);                  // v2 = output
}